// round 4
// baseline (speedup 1.0000x reference)
#include <cuda_runtime.h>
#include <cuda_bf16.h>

// ---------------- problem constants ----------------
#define BB      2
#define LL      2048
#define DM      2048
#define HH      64
#define PP      64
#define NST     128
#define KK      4
#define CHUNK   256
#define CC      8            // LL / CHUNK
#define DI      4096         // H*P
#define CONV    4352         // DI + 2*NST
#define PROJ    8512         // DI + CONV + HH
#define EPSV    1e-5f

// ---------------- scratch (static device memory) ---------------------------
__device__ float g_proj[(size_t)BB * LL * PROJ];
__device__ float g_hbc [(size_t)BB * LL * CONV];
__device__ float g_dt  [(size_t)BB * LL * HH];
__device__ float g_cum [(size_t)BB * LL * HH];
__device__ float g_s   [(size_t)BB * CC * CHUNK * CHUNK];
__device__ float g_states[(size_t)BB * CC * HH * PP * NST];
__device__ float g_prev  [(size_t)BB * CC * HH * PP * NST];
__device__ float g_y   [(size_t)BB * LL * DI];

// ---------------- tf32 helpers ----------------------------------------------
__device__ __forceinline__ unsigned f2tf32(float f) {
    unsigned r;
    asm("cvt.rna.tf32.f32 %0, %1;" : "=r"(r) : "f"(f));
    return r;
}

// ---------------- TF32 GEMM v3: 128 thr, 128x128x16, 64x64 warp tiles -------
// 4 warps (2x2), each warp 64x64 via m16n8k8 mma (4 mt x 8 nt).
// Double-buffered smem; conflict-free fragment strides (20 / 136).
__global__ __launch_bounds__(128) void tf32_gemm_kernel(
    const float* __restrict__ A, const float* __restrict__ B,
    float* __restrict__ C, int M, int N, int Kd)
{
    __shared__ unsigned As[2][128][20];   // [m][k]
    __shared__ unsigned Bs[2][16][136];   // [k][n]

    const int tid  = threadIdx.x;
    const int lane = tid & 31;
    const int warp = tid >> 5;
    const int wm = (warp >> 1) * 64;
    const int wn = (warp & 1) * 64;
    const int row0 = blockIdx.y * 128, col0 = blockIdx.x * 128;

    const int g  = lane >> 2;
    const int t4 = lane & 3;

    const int ar = tid >> 2;              // 0..31 (+32q)
    const int ac = (tid & 3) * 4;
    const int br = tid >> 5;              // 0..3 (+4q)
    const int bc = lane * 4;
    const bool bOk = (col0 + bc + 3) < N;

    float acc[4][8][4];
#pragma unroll
    for (int m = 0; m < 4; m++)
#pragma unroll
        for (int n = 0; n < 8; n++)
#pragma unroll
            for (int q = 0; q < 4; q++) acc[m][n][q] = 0.f;

    float4 ra[4], rb[4];
#pragma unroll
    for (int q = 0; q < 4; q++) {
        ra[q] = *(const float4*)&A[(size_t)(row0 + ar + q * 32) * Kd + ac];
        rb[q] = bOk ? *(const float4*)&B[(size_t)(br + q * 4) * N + col0 + bc]
                    : make_float4(0, 0, 0, 0);
    }
#pragma unroll
    for (int q = 0; q < 4; q++) {
        *(uint4*)&As[0][ar + q * 32][ac] =
            make_uint4(f2tf32(ra[q].x), f2tf32(ra[q].y), f2tf32(ra[q].z), f2tf32(ra[q].w));
        *(uint4*)&Bs[0][br + q * 4][bc] =
            make_uint4(f2tf32(rb[q].x), f2tf32(rb[q].y), f2tf32(rb[q].z), f2tf32(rb[q].w));
    }
    __syncthreads();

    int buf = 0;
    for (int k0 = 0; k0 < Kd; k0 += 16) {
        const bool more = (k0 + 16) < Kd;
        if (more) {
            int kn = k0 + 16;
#pragma unroll
            for (int q = 0; q < 4; q++) {
                ra[q] = *(const float4*)&A[(size_t)(row0 + ar + q * 32) * Kd + kn + ac];
                rb[q] = bOk ? *(const float4*)&B[(size_t)(kn + br + q * 4) * N + col0 + bc]
                            : make_float4(0, 0, 0, 0);
            }
        }

#pragma unroll
        for (int ks = 0; ks < 16; ks += 8) {
            unsigned af[4][4], bf[8][2];
#pragma unroll
            for (int mt = 0; mt < 4; mt++) {
                int r = wm + mt * 16;
                af[mt][0] = As[buf][r + g][ks + t4];
                af[mt][1] = As[buf][r + g + 8][ks + t4];
                af[mt][2] = As[buf][r + g][ks + t4 + 4];
                af[mt][3] = As[buf][r + g + 8][ks + t4 + 4];
            }
#pragma unroll
            for (int nt = 0; nt < 8; nt++) {
                int cB = wn + nt * 8 + g;
                bf[nt][0] = Bs[buf][ks + t4][cB];
                bf[nt][1] = Bs[buf][ks + t4 + 4][cB];
            }
#pragma unroll
            for (int mt = 0; mt < 4; mt++)
#pragma unroll
                for (int nt = 0; nt < 8; nt++) {
                    asm volatile(
                        "mma.sync.aligned.m16n8k8.row.col.f32.tf32.tf32.f32 "
                        "{%0,%1,%2,%3}, {%4,%5,%6,%7}, {%8,%9}, {%0,%1,%2,%3};"
                        : "+f"(acc[mt][nt][0]), "+f"(acc[mt][nt][1]),
                          "+f"(acc[mt][nt][2]), "+f"(acc[mt][nt][3])
                        : "r"(af[mt][0]), "r"(af[mt][1]),
                          "r"(af[mt][2]), "r"(af[mt][3]),
                          "r"(bf[nt][0]), "r"(bf[nt][1]));
                }
        }

        if (more) {
            int nb = buf ^ 1;
#pragma unroll
            for (int q = 0; q < 4; q++) {
                *(uint4*)&As[nb][ar + q * 32][ac] =
                    make_uint4(f2tf32(ra[q].x), f2tf32(ra[q].y), f2tf32(ra[q].z), f2tf32(ra[q].w));
                *(uint4*)&Bs[nb][br + q * 4][bc] =
                    make_uint4(f2tf32(rb[q].x), f2tf32(rb[q].y), f2tf32(rb[q].z), f2tf32(rb[q].w));
            }
            __syncthreads();
            buf = nb;
        }
    }

#pragma unroll
    for (int mt = 0; mt < 4; mt++) {
        int r = row0 + wm + mt * 16 + g;
#pragma unroll
        for (int nt = 0; nt < 8; nt++) {
            int cidx = col0 + wn + nt * 8 + t4 * 2;
            if (cidx < N) {
                *(float2*)&C[(size_t)r * N + cidx] = make_float2(acc[mt][nt][0], acc[mt][nt][1]);
                *(float2*)&C[(size_t)(r + 8) * N + cidx] = make_float2(acc[mt][nt][2], acc[mt][nt][3]);
            }
        }
    }
}

// ---------------- depthwise causal conv (K=4) + bias + SiLU ----------------
__global__ void conv_silu_kernel(const float* __restrict__ conv_w,
                                 const float* __restrict__ conv_b)
{
    size_t idx = (size_t)blockIdx.x * blockDim.x + threadIdx.x;
    const size_t total = (size_t)BB * LL * CONV;
    if (idx >= total) return;
    int ch = (int)(idx % CONV);
    size_t bl = idx / CONV;
    int l = (int)(bl % LL);

    float acc = conv_b[ch];
#pragma unroll
    for (int k = 0; k < KK; k++) {
        int ls = l - (KK - 1) + k;
        if (ls >= 0)
            acc += g_proj[(bl - (KK - 1) + k) * PROJ + DI + ch] * conv_w[ch * KK + k];
    }
    g_hbc[idx] = acc / (1.f + __expf(-acc));
}

// ---------------- dt = softplus(raw + bias); cum = chunk-cumsum(dt*A) ------
__global__ void dtcum_kernel(const float* __restrict__ dt_bias,
                             const float* __restrict__ A_log)
{
    int gw   = (blockIdx.x * blockDim.x + threadIdx.x) >> 5;
    int lane = threadIdx.x & 31;
    if (gw >= BB * CC * HH) return;
    int h  = gw % HH;
    int bc = gw / HH;
    int c  = bc % CC;
    int b  = bc / CC;

    float bias = dt_bias[h];
    float Ah   = -__expf(A_log[h]);
    float carry = 0.f;

    for (int t = 0; t < CHUNK / 32; t++) {
        int l = c * CHUNK + t * 32 + lane;
        size_t row = (size_t)b * LL + l;
        float v = g_proj[row * PROJ + DI + CONV + h] + bias;
        float dtv = (v > 20.f) ? v : log1pf(__expf(v));
        g_dt[row * HH + h] = dtv;
        float s = dtv * Ah;
#pragma unroll
        for (int off = 1; off < 32; off <<= 1) {
            float y = __shfl_up_sync(0xffffffffu, s, off);
            if (lane >= off) s += y;
        }
        float cum = carry + s;
        g_cum[row * HH + h] = cum;
        carry = __shfl_sync(0xffffffffu, cum, 31);
    }
}

// ---------------- head-independent scores: s[i,j] = C_i . B_j --------------
__global__ void scores_kernel()
{
    if (blockIdx.y < blockIdx.x) return;
    int bc = blockIdx.z;
    int b = bc / CC, c = bc % CC;
    int i0 = blockIdx.y * 32, j0 = blockIdx.x * 32;

    __shared__ float Cs[32][129];
    __shared__ float Bsh[32][129];

    int tx = threadIdx.x, ty = threadIdx.y;
    size_t baseRow = (size_t)b * LL + c * CHUNK;

#pragma unroll
    for (int q = 0; q < 4; q++) {
        int n = tx + 32 * q;
        Cs[ty][n]  = g_hbc[(baseRow + i0 + ty) * CONV + DI + NST + n];
        Bsh[ty][n] = g_hbc[(baseRow + j0 + ty) * CONV + DI + n];
    }
    __syncthreads();

    float acc = 0.f;
#pragma unroll
    for (int n = 0; n < NST; n++) acc += Cs[ty][n] * Bsh[tx][n];

    g_s[(size_t)bc * CHUNK * CHUNK + (size_t)(i0 + ty) * CHUNK + j0 + tx] = acc;
}

// ---------------- per-chunk states v2: 2p x 16n register blocking -----------
__global__ __launch_bounds__(256) void states_kernel()
{
    int bch = blockIdx.x;
    int h  = bch % HH;
    int bc = bch / HH;
    int c  = bc % CC, b = bc / CC;

    __shared__ float xs[32][66];
    __shared__ float Bsh[32][132];
    __shared__ float wsh[32];

    int tid = threadIdx.x;
    int p0 = (tid >> 3) * 2;          // 0..62 step 2
    int n0 = (tid & 7) * 16;          // 0..112 step 16
    size_t baseRow = (size_t)b * LL + c * CHUNK;
    float cumlast = g_cum[(baseRow + CHUNK - 1) * HH + h];

    float acc0[16], acc1[16];
#pragma unroll
    for (int k = 0; k < 16; k++) { acc0[k] = 0.f; acc1[k] = 0.f; }

    for (int lt = 0; lt < CHUNK; lt += 32) {
        for (int q = tid; q < 32 * 64; q += 256) {
            int ll = q >> 6, pp = q & 63;
            xs[ll][pp] = g_hbc[(baseRow + lt + ll) * CONV + h * PP + pp];
        }
        for (int q = tid; q < 32 * 128; q += 256) {
            int ll = q >> 7, nn = q & 127;
            Bsh[ll][nn] = g_hbc[(baseRow + lt + ll) * CONV + DI + nn];
        }
        if (tid < 32) {
            size_t r = baseRow + lt + tid;
            wsh[tid] = __expf(cumlast - g_cum[r * HH + h]) * g_dt[r * HH + h];
        }
        __syncthreads();
#pragma unroll 2
        for (int ll = 0; ll < 32; ll++) {
            float w  = wsh[ll];
            float x0 = w * xs[ll][p0];
            float x1 = w * xs[ll][p0 + 1];
#pragma unroll
            for (int nq = 0; nq < 4; nq++) {
                float4 bv = *(const float4*)&Bsh[ll][n0 + nq * 4];
                acc0[nq*4+0] += x0 * bv.x; acc0[nq*4+1] += x0 * bv.y;
                acc0[nq*4+2] += x0 * bv.z; acc0[nq*4+3] += x0 * bv.w;
                acc1[nq*4+0] += x1 * bv.x; acc1[nq*4+1] += x1 * bv.y;
                acc1[nq*4+2] += x1 * bv.z; acc1[nq*4+3] += x1 * bv.w;
            }
        }
        __syncthreads();
    }

    size_t ob0 = ((size_t)bch * PP + p0) * NST + n0;
#pragma unroll
    for (int nq = 0; nq < 4; nq++) {
        *(float4*)&g_states[ob0 + nq * 4] =
            make_float4(acc0[nq*4+0], acc0[nq*4+1], acc0[nq*4+2], acc0[nq*4+3]);
        *(float4*)&g_states[ob0 + NST + nq * 4] =
            make_float4(acc1[nq*4+0], acc1[nq*4+1], acc1[nq*4+2], acc1[nq*4+3]);
    }
}

// ---------------- inter-chunk scan ------------------------------------------
__global__ void scan_kernel()
{
    int idx = blockIdx.x * blockDim.x + threadIdx.x;
    if (idx >= BB * HH * PP * NST) return;
    int n = idx & 127;
    int p = (idx >> 7) & 63;
    int h = (idx >> 13) & 63;
    int b = idx >> 19;

    float prev = 0.f;
#pragma unroll
    for (int c = 0; c < CC; c++) {
        size_t sidx = ((((size_t)(b * CC + c) * HH + h) * PP + p) * NST) + n;
        g_prev[sidx] = prev;
        float cd = __expf(g_cum[((size_t)b * LL + c * CHUNK + CHUNK - 1) * HH + h]);
        prev = cd * prev + g_states[sidx];
    }
}

// ---------------- ycomb: register-blocked + factorized exp ------------------
__global__ __launch_bounds__(256) void ycomb_kernel(const float* __restrict__ D_param)
{
    int blk = blockIdx.x;
    int it  = blk & 3;
    int bch = blk >> 2;
    int h  = bch % HH;
    int bc = bch / HH;
    int c  = bc % CC, b = bc / CC;

    __shared__ float sm[2 * 64 * 68];
    __shared__ float s_cumj[64], s_dtj[64], s_wj[64];
    const int XOFF = 64 * 68;

    const int tid = threadIdx.x;
    const int p0  = (tid & 7) * 8;
    const int ig  = tid >> 3;
    const int il0 = ig * 2, il1 = il0 + 1;

    size_t baseRow = (size_t)b * LL + c * CHUNK;
    const int gi0 = it * 64 + il0;
    const float cumi0 = g_cum[(baseRow + gi0) * HH + h];
    const float cumi1 = g_cum[(baseRow + gi0 + 1) * HH + h];

    float acc0[8], acc1[8];
#pragma unroll
    for (int q = 0; q < 8; q++) { acc0[q] = 0.f; acc1[q] = 0.f; }

    for (int jt = 0; jt <= it; jt++) {
        for (int q = tid; q < 64 * 16; q += 256) {
            int r = q >> 4, c4 = (q & 15) * 4;
            float4 v = *(const float4*)&g_s[((size_t)bc * CHUNK + it * 64 + r) * CHUNK + jt * 64 + c4];
            *(float4*)&sm[r * 68 + c4] = v;
            float4 xv = *(const float4*)&g_hbc[(baseRow + jt * 64 + r) * CONV + h * PP + c4];
            *(float4*)&sm[XOFF + r * 68 + c4] = xv;
        }
        if (tid < 64) {
            size_t r = baseRow + jt * 64 + tid;
            s_cumj[tid] = g_cum[r * HH + h];
            s_dtj[tid]  = g_dt[r * HH + h];
        }
        __syncthreads();
        float cm = s_cumj[63];
        if (jt < it && tid < 64)
            s_wj[tid] = __expf(cm - s_cumj[tid]) * s_dtj[tid];
        __syncthreads();

        if (jt < it) {
            float E0 = __expf(cumi0 - cm);
            float E1 = __expf(cumi1 - cm);
#pragma unroll 4
            for (int jj = 0; jj < 64; jj++) {
                float wj = s_wj[jj];
                float w0 = sm[il0 * 68 + jj] * wj * E0;
                float w1 = sm[il1 * 68 + jj] * wj * E1;
                float4 xa = *(const float4*)&sm[XOFF + jj * 68 + p0];
                float4 xb = *(const float4*)&sm[XOFF + jj * 68 + p0 + 4];
                acc0[0] += w0 * xa.x; acc0[1] += w0 * xa.y; acc0[2] += w0 * xa.z; acc0[3] += w0 * xa.w;
                acc0[4] += w0 * xb.x; acc0[5] += w0 * xb.y; acc0[6] += w0 * xb.z; acc0[7] += w0 * xb.w;
                acc1[0] += w1 * xa.x; acc1[1] += w1 * xa.y; acc1[2] += w1 * xa.z; acc1[3] += w1 * xa.w;
                acc1[4] += w1 * xb.x; acc1[5] += w1 * xb.y; acc1[6] += w1 * xb.z; acc1[7] += w1 * xb.w;
            }
        } else {
            for (int jj = 0; jj < 64; jj++) {
                float cj = s_cumj[jj], dj = s_dtj[jj];
                float w0 = (jj <= il0) ? sm[il0 * 68 + jj] * __expf(cumi0 - cj) * dj : 0.f;
                float w1 = (jj <= il1) ? sm[il1 * 68 + jj] * __expf(cumi1 - cj) * dj : 0.f;
                float4 xa = *(const float4*)&sm[XOFF + jj * 68 + p0];
                float4 xb = *(const float4*)&sm[XOFF + jj * 68 + p0 + 4];
                acc0[0] += w0 * xa.x; acc0[1] += w0 * xa.y; acc0[2] += w0 * xa.z; acc0[3] += w0 * xa.w;
                acc0[4] += w0 * xb.x; acc0[5] += w0 * xb.y; acc0[6] += w0 * xb.z; acc0[7] += w0 * xb.w;
                acc1[0] += w1 * xa.x; acc1[1] += w1 * xa.y; acc1[2] += w1 * xa.z; acc1[3] += w1 * xa.w;
                acc1[4] += w1 * xb.x; acc1[5] += w1 * xb.y; acc1[6] += w1 * xb.z; acc1[7] += w1 * xb.w;
            }
        }
        __syncthreads();
    }

    {
        size_t pbase = (size_t)bch * PP * NST;
        for (int q = tid; q < 64 * 32; q += 256) {
            int p = q >> 5, n4 = (q & 31) * 4;
            float4 v = *(const float4*)&g_prev[pbase + (size_t)p * NST + n4];
            sm[(n4 + 0) * 68 + p] = v.x;
            sm[(n4 + 1) * 68 + p] = v.y;
            sm[(n4 + 2) * 68 + p] = v.z;
            sm[(n4 + 3) * 68 + p] = v.w;
        }
        __syncthreads();

        float e0 = __expf(cumi0);
        float e1 = __expf(cumi1);
        const float* C0 = &g_hbc[(baseRow + gi0) * CONV + DI + NST];
        const float* C1 = C0 + CONV;
#pragma unroll 2
        for (int n = 0; n < NST; n += 4) {
            float4 ca = *(const float4*)&C0[n];
            float4 cb = *(const float4*)&C1[n];
#pragma unroll
            for (int k = 0; k < 4; k++) {
                float cav = (k == 0) ? ca.x : (k == 1) ? ca.y : (k == 2) ? ca.z : ca.w;
                float cbv = (k == 0) ? cb.x : (k == 1) ? cb.y : (k == 2) ? cb.z : cb.w;
                float w0 = e0 * cav, w1 = e1 * cbv;
                const float* xp = &sm[(n + k) * 68 + p0];
                float4 xa = *(const float4*)xp;
                float4 xb = *(const float4*)(xp + 4);
                acc0[0] += w0 * xa.x; acc0[1] += w0 * xa.y; acc0[2] += w0 * xa.z; acc0[3] += w0 * xa.w;
                acc0[4] += w0 * xb.x; acc0[5] += w0 * xb.y; acc0[6] += w0 * xb.z; acc0[7] += w0 * xb.w;
                acc1[0] += w1 * xa.x; acc1[1] += w1 * xa.y; acc1[2] += w1 * xa.z; acc1[3] += w1 * xa.w;
                acc1[4] += w1 * xb.x; acc1[5] += w1 * xb.y; acc1[6] += w1 * xb.z; acc1[7] += w1 * xb.w;
            }
        }
    }

    {
        float Dh = D_param[h];
        const float* x0 = &g_hbc[(baseRow + gi0) * CONV + h * PP + p0];
        const float* x1 = x0 + CONV;
        float* y0 = &g_y[(baseRow + gi0) * DI + h * PP + p0];
        float* y1 = y0 + DI;
        float4 o;
        o = make_float4(acc0[0] + Dh * x0[0], acc0[1] + Dh * x0[1], acc0[2] + Dh * x0[2], acc0[3] + Dh * x0[3]);
        *(float4*)y0 = o;
        o = make_float4(acc0[4] + Dh * x0[4], acc0[5] + Dh * x0[5], acc0[6] + Dh * x0[6], acc0[7] + Dh * x0[7]);
        *(float4*)(y0 + 4) = o;
        o = make_float4(acc1[0] + Dh * x1[0], acc1[1] + Dh * x1[1], acc1[2] + Dh * x1[2], acc1[3] + Dh * x1[3]);
        *(float4*)y1 = o;
        o = make_float4(acc1[4] + Dh * x1[4], acc1[5] + Dh * x1[5], acc1[6] + Dh * x1[6], acc1[7] + Dh * x1[7]);
        *(float4*)(y1 + 4) = o;
    }
}

// ---------------- gated RMSNorm ----------------------------------------------
__global__ __launch_bounds__(256) void gatenorm_kernel(const float* __restrict__ norm_w)
{
    int row = blockIdx.x;
    __shared__ float sh[DI];
    __shared__ float red[256];

    const float* yrow = &g_y[(size_t)row * DI];
    const float* grow = &g_proj[(size_t)row * PROJ];

    float local = 0.f;
    for (int d = threadIdx.x; d < DI; d += 256) {
        float g  = grow[d];
        float hv = yrow[d] * (g / (1.f + __expf(-g)));
        sh[d] = hv;
        local += hv * hv;
    }
    red[threadIdx.x] = local;
    __syncthreads();
    for (int s = 128; s > 0; s >>= 1) {
        if (threadIdx.x < s) red[threadIdx.x] += red[threadIdx.x + s];
        __syncthreads();
    }
    float rms = rsqrtf(red[0] / (float)DI + EPSV);

    float* orow = &g_y[(size_t)row * DI];
    for (int d = threadIdx.x; d < DI; d += 256)
        orow[d] = sh[d] * rms * norm_w[d];
}

// ---------------- launcher ---------------------------------------------------
extern "C" void kernel_launch(void* const* d_in, const int* in_sizes, int n_in,
                              void* d_out, int out_size)
{
    const float* hs       = (const float*)d_in[0];
    const float* in_proj  = (const float*)d_in[1];
    const float* conv_w   = (const float*)d_in[2];
    const float* conv_b   = (const float*)d_in[3];
    const float* dt_bias  = (const float*)d_in[4];
    const float* A_log    = (const float*)d_in[5];
    const float* D_param  = (const float*)d_in[6];
    const float* norm_w   = (const float*)d_in[7];
    const float* out_proj = (const float*)d_in[8];
    float* out = (float*)d_out;

    float* proj_ptr;   cudaGetSymbolAddress((void**)&proj_ptr, g_proj);
    float* y_ptr;      cudaGetSymbolAddress((void**)&y_ptr, g_y);

    const int M = BB * LL;   // 4096

    // 1) in-projection GEMM (tf32 v3)
    {
        dim3 grid((PROJ + 127) / 128, M / 128);
        tf32_gemm_kernel<<<grid, 128>>>(hs, in_proj, proj_ptr, M, PROJ, DM);
    }
    // 2) depthwise conv + silu
    {
        size_t total = (size_t)BB * LL * CONV;
        conv_silu_kernel<<<(unsigned)((total + 255) / 256), 256>>>(conv_w, conv_b);
    }
    // 3) dt softplus + chunk cumsum
    dtcum_kernel<<<(BB * CC * HH * 32 + 255) / 256, 256>>>(dt_bias, A_log);
    // 4) head-independent CB scores
    {
        dim3 grid(CHUNK / 32, CHUNK / 32, BB * CC);
        scores_kernel<<<grid, dim3(32, 32)>>>();
    }
    // 5) per-chunk states (register-blocked)
    states_kernel<<<BB * CC * HH, 256>>>();
    // 6) inter-chunk scan
    scan_kernel<<<(BB * HH * PP * NST + 255) / 256, 256>>>();
    // 7) Y = diag + off + D*x
    ycomb_kernel<<<BB * CC * HH * 4, 256>>>(D_param);
    // 8) gated RMSNorm
    gatenorm_kernel<<<BB * LL, 256>>>(norm_w);
    // 9) out-projection GEMM (tf32 v3)
    {
        dim3 grid(DM / 128, M / 128);
        tf32_gemm_kernel<<<grid, 128>>>(y_ptr, out_proj, out, M, DM, DI);
    }
    (void)in_sizes; (void)n_in; (void)out_size;
}

// round 7
// speedup vs baseline: 1.0331x; 1.0331x over previous
#include <cuda_runtime.h>
#include <cuda_bf16.h>
#include <cstdint>

// ---------------- problem constants ----------------
#define BB      2
#define LL      2048
#define DM      2048
#define HH      64
#define PP      64
#define NST     128
#define KK      4
#define CHUNK   256
#define CC      8            // LL / CHUNK
#define DI      4096         // H*P
#define CONV    4352         // DI + 2*NST
#define PROJ    8512         // DI + CONV + HH
#define EPSV    1e-5f

// ---------------- scratch (static device memory) ---------------------------
__device__ float g_proj[(size_t)BB * LL * PROJ];
__device__ float g_hbc [(size_t)BB * LL * CONV];
__device__ float g_dt  [(size_t)BB * LL * HH];
__device__ float g_cum [(size_t)BB * LL * HH];
__device__ float g_s   [(size_t)BB * CC * CHUNK * CHUNK];
__device__ float g_states[(size_t)BB * CC * HH * PP * NST];
__device__ float g_prev  [(size_t)BB * CC * HH * PP * NST];
__device__ float g_y   [(size_t)BB * LL * DI];

// ---------------- helpers ----------------------------------------------------
__device__ __forceinline__ unsigned f2tf32(float f) {
    unsigned r;
    asm("cvt.rna.tf32.f32 %0, %1;" : "=r"(r) : "f"(f));
    return r;
}
typedef unsigned long long ull;
__device__ __forceinline__ ull pack2(float lo, float hi) {
    ull r;
    asm("mov.b64 %0, {%1, %2};" : "=l"(r) : "f"(lo), "f"(hi));
    return r;
}
__device__ __forceinline__ void fma2(ull& d, ull a, ull b) {
    asm("fma.rn.f32x2 %0, %1, %2, %0;" : "+l"(d) : "l"(a), "l"(b));
}
__device__ __forceinline__ float2 unpack2(ull v) {
    float2 f;
    asm("mov.b64 {%0, %1}, %2;" : "=f"(f.x), "=f"(f.y) : "l"(v));
    return f;
}

// ---------------- TF32 GEMM v2 (round-3 exact): 256 thr, 128x128x16 ---------
__global__ __launch_bounds__(256) void tf32_gemm_kernel(
    const float* __restrict__ A, const float* __restrict__ B,
    float* __restrict__ C, int M, int N, int Kd)
{
    __shared__ unsigned As[2][128][20];   // [m][k], stride 20
    __shared__ unsigned Bs[2][16][136];   // [k][n], stride 136

    const int tid  = threadIdx.x;
    const int lane = tid & 31;
    const int warp = tid >> 5;
    const int wm = (warp >> 2) * 64;      // warp M offset (0/64)
    const int wn = (warp & 3) * 32;       // warp N offset (0/32/64/96)
    const int row0 = blockIdx.y * 128, col0 = blockIdx.x * 128;

    const int g  = lane >> 2;
    const int t4 = lane & 3;

    const int ar = tid >> 2;
    const int ac = (tid & 3) * 4;
    const int br = tid >> 5;
    const int bc = (tid & 31) * 4;
    const bool bOk = (col0 + bc + 3) < N;

    float acc[4][4][4];
#pragma unroll
    for (int m = 0; m < 4; m++)
#pragma unroll
        for (int n = 0; n < 4; n++)
#pragma unroll
            for (int q = 0; q < 4; q++) acc[m][n][q] = 0.f;

    float4 ra[2], rb[2];
    ra[0] = *(const float4*)&A[(size_t)(row0 + ar) * Kd + ac];
    ra[1] = *(const float4*)&A[(size_t)(row0 + ar + 64) * Kd + ac];
    rb[0] = bOk ? *(const float4*)&B[(size_t)br * N + col0 + bc] : make_float4(0,0,0,0);
    rb[1] = bOk ? *(const float4*)&B[(size_t)(br + 8) * N + col0 + bc] : make_float4(0,0,0,0);
    {
        *(uint4*)&As[0][ar][ac]      = make_uint4(f2tf32(ra[0].x), f2tf32(ra[0].y), f2tf32(ra[0].z), f2tf32(ra[0].w));
        *(uint4*)&As[0][ar + 64][ac] = make_uint4(f2tf32(ra[1].x), f2tf32(ra[1].y), f2tf32(ra[1].z), f2tf32(ra[1].w));
        *(uint4*)&Bs[0][br][bc]      = make_uint4(f2tf32(rb[0].x), f2tf32(rb[0].y), f2tf32(rb[0].z), f2tf32(rb[0].w));
        *(uint4*)&Bs[0][br + 8][bc]  = make_uint4(f2tf32(rb[1].x), f2tf32(rb[1].y), f2tf32(rb[1].z), f2tf32(rb[1].w));
    }
    __syncthreads();

    int buf = 0;
    for (int k0 = 0; k0 < Kd; k0 += 16) {
        const bool more = (k0 + 16) < Kd;
        if (more) {
            int kn = k0 + 16;
            ra[0] = *(const float4*)&A[(size_t)(row0 + ar) * Kd + kn + ac];
            ra[1] = *(const float4*)&A[(size_t)(row0 + ar + 64) * Kd + kn + ac];
            rb[0] = bOk ? *(const float4*)&B[(size_t)(kn + br) * N + col0 + bc] : make_float4(0,0,0,0);
            rb[1] = bOk ? *(const float4*)&B[(size_t)(kn + br + 8) * N + col0 + bc] : make_float4(0,0,0,0);
        }

#pragma unroll
        for (int ks = 0; ks < 16; ks += 8) {
            unsigned af[4][4], bf[4][2];
#pragma unroll
            for (int mt = 0; mt < 4; mt++) {
                int r = wm + mt * 16;
                af[mt][0] = As[buf][r + g][ks + t4];
                af[mt][1] = As[buf][r + g + 8][ks + t4];
                af[mt][2] = As[buf][r + g][ks + t4 + 4];
                af[mt][3] = As[buf][r + g + 8][ks + t4 + 4];
            }
#pragma unroll
            for (int nt = 0; nt < 4; nt++) {
                int cB = wn + nt * 8 + g;
                bf[nt][0] = Bs[buf][ks + t4][cB];
                bf[nt][1] = Bs[buf][ks + t4 + 4][cB];
            }
#pragma unroll
            for (int mt = 0; mt < 4; mt++)
#pragma unroll
                for (int nt = 0; nt < 4; nt++) {
                    asm volatile(
                        "mma.sync.aligned.m16n8k8.row.col.f32.tf32.tf32.f32 "
                        "{%0,%1,%2,%3}, {%4,%5,%6,%7}, {%8,%9}, {%0,%1,%2,%3};"
                        : "+f"(acc[mt][nt][0]), "+f"(acc[mt][nt][1]),
                          "+f"(acc[mt][nt][2]), "+f"(acc[mt][nt][3])
                        : "r"(af[mt][0]), "r"(af[mt][1]),
                          "r"(af[mt][2]), "r"(af[mt][3]),
                          "r"(bf[nt][0]), "r"(bf[nt][1]));
                }
        }

        if (more) {
            int nb = buf ^ 1;
            *(uint4*)&As[nb][ar][ac]      = make_uint4(f2tf32(ra[0].x), f2tf32(ra[0].y), f2tf32(ra[0].z), f2tf32(ra[0].w));
            *(uint4*)&As[nb][ar + 64][ac] = make_uint4(f2tf32(ra[1].x), f2tf32(ra[1].y), f2tf32(ra[1].z), f2tf32(ra[1].w));
            *(uint4*)&Bs[nb][br][bc]      = make_uint4(f2tf32(rb[0].x), f2tf32(rb[0].y), f2tf32(rb[0].z), f2tf32(rb[0].w));
            *(uint4*)&Bs[nb][br + 8][bc]  = make_uint4(f2tf32(rb[1].x), f2tf32(rb[1].y), f2tf32(rb[1].z), f2tf32(rb[1].w));
            __syncthreads();
            buf = nb;
        }
    }

#pragma unroll
    for (int mt = 0; mt < 4; mt++) {
        int r = row0 + wm + mt * 16 + g;
#pragma unroll
        for (int nt = 0; nt < 4; nt++) {
            int cidx = col0 + wn + nt * 8 + t4 * 2;
            if (cidx < N) {
                *(float2*)&C[(size_t)r * N + cidx] = make_float2(acc[mt][nt][0], acc[mt][nt][1]);
                *(float2*)&C[(size_t)(r + 8) * N + cidx] = make_float2(acc[mt][nt][2], acc[mt][nt][3]);
            }
        }
    }
}

// ---------------- conv v2: smem-tiled depthwise conv + bias + SiLU ----------
__global__ __launch_bounds__(256) void conv_silu_kernel(
    const float* __restrict__ conv_w, const float* __restrict__ conv_b)
{
    __shared__ float sm[35][256];
    const int tid = threadIdx.x;
    const int ch  = blockIdx.x * 256 + tid;
    const int l0  = blockIdx.y * 32;
    const int b   = blockIdx.z;

    const float* src = &g_proj[((size_t)b * LL) * PROJ + DI + ch];
#pragma unroll
    for (int r = 0; r < 35; r++) {
        int l = l0 - 3 + r;
        sm[r][tid] = (l >= 0) ? src[(size_t)l * PROJ] : 0.f;
    }
    float4 wv = *(const float4*)&conv_w[ch * 4];
    float bias = conv_b[ch];
    __syncthreads();

    float* dst = &g_hbc[((size_t)b * LL + l0) * CONV + ch];
#pragma unroll
    for (int j = 0; j < 32; j++) {
        float acc = bias;
        acc += sm[j][tid]     * wv.x;
        acc += sm[j + 1][tid] * wv.y;
        acc += sm[j + 2][tid] * wv.z;
        acc += sm[j + 3][tid] * wv.w;
        dst[(size_t)j * CONV] = acc / (1.f + __expf(-acc));
    }
}

// ---------------- dt softplus + chunk cumsum --------------------------------
__global__ void dtcum_kernel(const float* __restrict__ dt_bias,
                             const float* __restrict__ A_log)
{
    int gw   = (blockIdx.x * blockDim.x + threadIdx.x) >> 5;
    int lane = threadIdx.x & 31;
    if (gw >= BB * CC * HH) return;
    int h  = gw % HH;
    int bc = gw / HH;
    int c  = bc % CC;
    int b  = bc / CC;

    float bias = dt_bias[h];
    float Ah   = -__expf(A_log[h]);
    float carry = 0.f;

    for (int t = 0; t < CHUNK / 32; t++) {
        int l = c * CHUNK + t * 32 + lane;
        size_t row = (size_t)b * LL + l;
        float v = g_proj[row * PROJ + DI + CONV + h] + bias;
        float dtv = (v > 20.f) ? v : log1pf(__expf(v));
        g_dt[row * HH + h] = dtv;
        float s = dtv * Ah;
#pragma unroll
        for (int off = 1; off < 32; off <<= 1) {
            float y = __shfl_up_sync(0xffffffffu, s, off);
            if (lane >= off) s += y;
        }
        float cum = carry + s;
        g_cum[row * HH + h] = cum;
        carry = __shfl_sync(0xffffffffu, cum, 31);
    }
}

// ---------------- head-independent scores: s[i,j] = C_i . B_j --------------
__global__ void scores_kernel()
{
    if (blockIdx.y < blockIdx.x) return;
    int bc = blockIdx.z;
    int b = bc / CC, c = bc % CC;
    int i0 = blockIdx.y * 32, j0 = blockIdx.x * 32;

    __shared__ float Cs[32][129];
    __shared__ float Bsh[32][129];

    int tx = threadIdx.x, ty = threadIdx.y;
    size_t baseRow = (size_t)b * LL + c * CHUNK;

#pragma unroll
    for (int q = 0; q < 4; q++) {
        int n = tx + 32 * q;
        Cs[ty][n]  = g_hbc[(baseRow + i0 + ty) * CONV + DI + NST + n];
        Bsh[ty][n] = g_hbc[(baseRow + j0 + ty) * CONV + DI + n];
    }
    __syncthreads();

    float acc = 0.f;
#pragma unroll
    for (int n = 0; n < NST; n++) acc += Cs[ty][n] * Bsh[tx][n];

    g_s[(size_t)bc * CHUNK * CHUNK + (size_t)(i0 + ty) * CHUNK + j0 + tx] = acc;
}

// ---------------- per-chunk states: 2p x 16n, f32x2 FMA ----------------------
__global__ __launch_bounds__(256) void states_kernel()
{
    int bch = blockIdx.x;
    int h  = bch % HH;
    int bc = bch / HH;
    int c  = bc % CC, b = bc / CC;

    __shared__ __align__(16) float xs[32][66];
    __shared__ __align__(16) float Bsh[32][132];
    __shared__ float wsh[32];

    int tid = threadIdx.x;
    int p0 = (tid >> 3) * 2;
    int n0 = (tid & 7) * 16;
    size_t baseRow = (size_t)b * LL + c * CHUNK;
    float cumlast = g_cum[(baseRow + CHUNK - 1) * HH + h];

    ull A0[8], A1[8];
#pragma unroll
    for (int k = 0; k < 8; k++) { A0[k] = 0ULL; A1[k] = 0ULL; }

    for (int lt = 0; lt < CHUNK; lt += 32) {
        for (int q = tid; q < 32 * 64; q += 256) {
            int ll = q >> 6, pp = q & 63;
            xs[ll][pp] = g_hbc[(baseRow + lt + ll) * CONV + h * PP + pp];
        }
        for (int q = tid; q < 32 * 128; q += 256) {
            int ll = q >> 7, nn = q & 127;
            Bsh[ll][nn] = g_hbc[(baseRow + lt + ll) * CONV + DI + nn];
        }
        if (tid < 32) {
            size_t r = baseRow + lt + tid;
            wsh[tid] = __expf(cumlast - g_cum[r * HH + h]) * g_dt[r * HH + h];
        }
        __syncthreads();
#pragma unroll 2
        for (int ll = 0; ll < 32; ll++) {
            float w  = wsh[ll];
            ull X0 = pack2(w * xs[ll][p0],     w * xs[ll][p0]);
            ull X1 = pack2(w * xs[ll][p0 + 1], w * xs[ll][p0 + 1]);
            const ulonglong2* bp = (const ulonglong2*)&Bsh[ll][n0];
#pragma unroll
            for (int j = 0; j < 4; j++) {
                ulonglong2 bv = bp[j];
                fma2(A0[j * 2],     X0, bv.x);
                fma2(A0[j * 2 + 1], X0, bv.y);
                fma2(A1[j * 2],     X1, bv.x);
                fma2(A1[j * 2 + 1], X1, bv.y);
            }
        }
        __syncthreads();
    }

    size_t ob0 = ((size_t)bch * PP + p0) * NST + n0;
#pragma unroll
    for (int j = 0; j < 4; j++) {
        float2 a = unpack2(A0[j * 2]), bq = unpack2(A0[j * 2 + 1]);
        *(float4*)&g_states[ob0 + j * 4] = make_float4(a.x, a.y, bq.x, bq.y);
        float2 c2 = unpack2(A1[j * 2]), d2 = unpack2(A1[j * 2 + 1]);
        *(float4*)&g_states[ob0 + NST + j * 4] = make_float4(c2.x, c2.y, d2.x, d2.y);
    }
}

// ---------------- inter-chunk scan ------------------------------------------
__global__ void scan_kernel()
{
    int idx = blockIdx.x * blockDim.x + threadIdx.x;
    if (idx >= BB * HH * PP * NST) return;
    int n = idx & 127;
    int p = (idx >> 7) & 63;
    int h = (idx >> 13) & 63;
    int b = idx >> 19;

    float prev = 0.f;
#pragma unroll
    for (int c = 0; c < CC; c++) {
        size_t sidx = ((((size_t)(b * CC + c) * HH + h) * PP + p) * NST) + n;
        g_prev[sidx] = prev;
        float cd = __expf(g_cum[((size_t)b * LL + c * CHUNK + CHUNK - 1) * HH + h]);
        prev = cd * prev + g_states[sidx];
    }
}

// ---------------- ycomb: register-blocked, factorized exp, f32x2 FMA --------
__global__ __launch_bounds__(256) void ycomb_kernel(const float* __restrict__ D_param)
{
    int blk = blockIdx.x;
    int it  = blk & 3;
    int bch = blk >> 2;
    int h  = bch % HH;
    int bc = bch / HH;
    int c  = bc % CC, b = bc / CC;

    __shared__ __align__(16) float sm[2 * 64 * 68];
    __shared__ float s_cumj[64], s_dtj[64], s_wj[64];
    const int XOFF = 64 * 68;

    const int tid = threadIdx.x;
    const int p0  = (tid & 7) * 8;
    const int ig  = tid >> 3;
    const int il0 = ig * 2, il1 = il0 + 1;

    size_t baseRow = (size_t)b * LL + c * CHUNK;
    const int gi0 = it * 64 + il0;
    const float cumi0 = g_cum[(baseRow + gi0) * HH + h];
    const float cumi1 = g_cum[(baseRow + gi0 + 1) * HH + h];

    ull a0[4], a1[4];
#pragma unroll
    for (int q = 0; q < 4; q++) { a0[q] = 0ULL; a1[q] = 0ULL; }

    for (int jt = 0; jt <= it; jt++) {
        for (int q = tid; q < 64 * 16; q += 256) {
            int r = q >> 4, c4 = (q & 15) * 4;
            float4 v = *(const float4*)&g_s[((size_t)bc * CHUNK + it * 64 + r) * CHUNK + jt * 64 + c4];
            *(float4*)&sm[r * 68 + c4] = v;
            float4 xv = *(const float4*)&g_hbc[(baseRow + jt * 64 + r) * CONV + h * PP + c4];
            *(float4*)&sm[XOFF + r * 68 + c4] = xv;
        }
        if (tid < 64) {
            size_t r = baseRow + jt * 64 + tid;
            s_cumj[tid] = g_cum[r * HH + h];
            s_dtj[tid]  = g_dt[r * HH + h];
        }
        __syncthreads();
        float cm = s_cumj[63];
        if (jt < it && tid < 64)
            s_wj[tid] = __expf(cm - s_cumj[tid]) * s_dtj[tid];
        __syncthreads();

        if (jt < it) {
            float E0 = __expf(cumi0 - cm);
            float E1 = __expf(cumi1 - cm);
#pragma unroll 4
            for (int jj = 0; jj < 64; jj++) {
                float wj = s_wj[jj];
                float w0 = sm[il0 * 68 + jj] * wj * E0;
                float w1 = sm[il1 * 68 + jj] * wj * E1;
                ull W0 = pack2(w0, w0), W1 = pack2(w1, w1);
                ulonglong2 xa = *(const ulonglong2*)&sm[XOFF + jj * 68 + p0];
                ulonglong2 xb = *(const ulonglong2*)&sm[XOFF + jj * 68 + p0 + 4];
                fma2(a0[0], W0, xa.x); fma2(a0[1], W0, xa.y);
                fma2(a0[2], W0, xb.x); fma2(a0[3], W0, xb.y);
                fma2(a1[0], W1, xa.x); fma2(a1[1], W1, xa.y);
                fma2(a1[2], W1, xb.x); fma2(a1[3], W1, xb.y);
            }
        } else {
            for (int jj = 0; jj < 64; jj++) {
                float cj = s_cumj[jj], dj = s_dtj[jj];
                float w0 = (jj <= il0) ? sm[il0 * 68 + jj] * __expf(cumi0 - cj) * dj : 0.f;
                float w1 = (jj <= il1) ? sm[il1 * 68 + jj] * __expf(cumi1 - cj) * dj : 0.f;
                ull W0 = pack2(w0, w0), W1 = pack2(w1, w1);
                ulonglong2 xa = *(const ulonglong2*)&sm[XOFF + jj * 68 + p0];
                ulonglong2 xb = *(const ulonglong2*)&sm[XOFF + jj * 68 + p0 + 4];
                fma2(a0[0], W0, xa.x); fma2(a0[1], W0, xa.y);
                fma2(a0[2], W0, xb.x); fma2(a0[3], W0, xb.y);
                fma2(a1[0], W1, xa.x); fma2(a1[1], W1, xa.y);
                fma2(a1[2], W1, xb.x); fma2(a1[3], W1, xb.y);
            }
        }
        __syncthreads();
    }

    // phase B: inter-chunk term via prev_states
    {
        size_t pbase = (size_t)bch * PP * NST;
        for (int q = tid; q < 64 * 32; q += 256) {
            int p = q >> 5, n4 = (q & 31) * 4;
            float4 v = *(const float4*)&g_prev[pbase + (size_t)p * NST + n4];
            sm[(n4 + 0) * 68 + p] = v.x;
            sm[(n4 + 1) * 68 + p] = v.y;
            sm[(n4 + 2) * 68 + p] = v.z;
            sm[(n4 + 3) * 68 + p] = v.w;
        }
        __syncthreads();

        float e0 = __expf(cumi0);
        float e1 = __expf(cumi1);
        const float* C0 = &g_hbc[(baseRow + gi0) * CONV + DI + NST];
        const float* C1 = C0 + CONV;
#pragma unroll 2
        for (int n = 0; n < NST; n += 4) {
            float4 ca = *(const float4*)&C0[n];
            float4 cb = *(const float4*)&C1[n];
#pragma unroll
            for (int k = 0; k < 4; k++) {
                float cav = (k == 0) ? ca.x : (k == 1) ? ca.y : (k == 2) ? ca.z : ca.w;
                float cbv = (k == 0) ? cb.x : (k == 1) ? cb.y : (k == 2) ? cb.z : cb.w;
                float w0 = e0 * cav, w1 = e1 * cbv;
                ull W0 = pack2(w0, w0), W1 = pack2(w1, w1);
                const float* xp = &sm[(n + k) * 68 + p0];
                ulonglong2 xa = *(const ulonglong2*)xp;
                ulonglong2 xb = *(const ulonglong2*)(xp + 4);   // FIX: was xp + 8
                fma2(a0[0], W0, xa.x); fma2(a0[1], W0, xa.y);
                fma2(a0[2], W0, xb.x); fma2(a0[3], W0, xb.y);
                fma2(a1[0], W1, xa.x); fma2(a1[1], W1, xa.y);
                fma2(a1[2], W1, xb.x); fma2(a1[3], W1, xb.y);
            }
        }
    }

    // phase C: + D*x, write
    {
        float Dh = D_param[h];
        const float* x0 = &g_hbc[(baseRow + gi0) * CONV + h * PP + p0];
        const float* x1 = x0 + CONV;
        float* y0 = &g_y[(baseRow + gi0) * DI + h * PP + p0];
        float* y1 = y0 + DI;
        float2 q0 = unpack2(a0[0]), q1 = unpack2(a0[1]), q2 = unpack2(a0[2]), q3 = unpack2(a0[3]);
        *(float4*)y0       = make_float4(q0.x + Dh * x0[0], q0.y + Dh * x0[1],
                                         q1.x + Dh * x0[2], q1.y + Dh * x0[3]);
        *(float4*)(y0 + 4) = make_float4(q2.x + Dh * x0[4], q2.y + Dh * x0[5],
                                         q3.x + Dh * x0[6], q3.y + Dh * x0[7]);
        float2 r0 = unpack2(a1[0]), r1 = unpack2(a1[1]), r2 = unpack2(a1[2]), r3 = unpack2(a1[3]);
        *(float4*)y1       = make_float4(r0.x + Dh * x1[0], r0.y + Dh * x1[1],
                                         r1.x + Dh * x1[2], r1.y + Dh * x1[3]);
        *(float4*)(y1 + 4) = make_float4(r2.x + Dh * x1[4], r2.y + Dh * x1[5],
                                         r3.x + Dh * x1[6], r3.y + Dh * x1[7]);
    }
}

// ---------------- gated RMSNorm ----------------------------------------------
__global__ __launch_bounds__(256) void gatenorm_kernel(const float* __restrict__ norm_w)
{
    int row = blockIdx.x;
    __shared__ float sh[DI];
    __shared__ float red[256];

    const float* yrow = &g_y[(size_t)row * DI];
    const float* grow = &g_proj[(size_t)row * PROJ];

    float local = 0.f;
    for (int d = threadIdx.x; d < DI; d += 256) {
        float g  = grow[d];
        float hv = yrow[d] * (g / (1.f + __expf(-g)));
        sh[d] = hv;
        local += hv * hv;
    }
    red[threadIdx.x] = local;
    __syncthreads();
    for (int s = 128; s > 0; s >>= 1) {
        if (threadIdx.x < s) red[threadIdx.x] += red[threadIdx.x + s];
        __syncthreads();
    }
    float rms = rsqrtf(red[0] / (float)DI + EPSV);

    float* orow = &g_y[(size_t)row * DI];
    for (int d = threadIdx.x; d < DI; d += 256)
        orow[d] = sh[d] * rms * norm_w[d];
}

// ---------------- launcher ---------------------------------------------------
extern "C" void kernel_launch(void* const* d_in, const int* in_sizes, int n_in,
                              void* d_out, int out_size)
{
    const float* hs       = (const float*)d_in[0];
    const float* in_proj  = (const float*)d_in[1];
    const float* conv_w   = (const float*)d_in[2];
    const float* conv_b   = (const float*)d_in[3];
    const float* dt_bias  = (const float*)d_in[4];
    const float* A_log    = (const float*)d_in[5];
    const float* D_param  = (const float*)d_in[6];
    const float* norm_w   = (const float*)d_in[7];
    const float* out_proj = (const float*)d_in[8];
    float* out = (float*)d_out;

    float* proj_ptr;   cudaGetSymbolAddress((void**)&proj_ptr, g_proj);
    float* y_ptr;      cudaGetSymbolAddress((void**)&y_ptr, g_y);

    const int M = BB * LL;   // 4096

    // 1) in-projection GEMM (tf32 tensor cores, double-buffered)
    {
        dim3 grid((PROJ + 127) / 128, M / 128);
        tf32_gemm_kernel<<<grid, 256>>>(hs, in_proj, proj_ptr, M, PROJ, DM);
    }
    // 2) depthwise conv + silu (smem-tiled)
    {
        dim3 grid(CONV / 256, LL / 32, BB);
        conv_silu_kernel<<<grid, 256>>>(conv_w, conv_b);
    }
    // 3) dt softplus + chunk cumsum
    dtcum_kernel<<<(BB * CC * HH * 32 + 255) / 256, 256>>>(dt_bias, A_log);
    // 4) head-independent CB scores
    {
        dim3 grid(CHUNK / 32, CHUNK / 32, BB * CC);
        scores_kernel<<<grid, dim3(32, 32)>>>();
    }
    // 5) per-chunk states (register-blocked, f32x2)
    states_kernel<<<BB * CC * HH, 256>>>();
    // 6) inter-chunk scan
    scan_kernel<<<(BB * HH * PP * NST + 255) / 256, 256>>>();
    // 7) Y = diag + off + D*x  (f32x2)
    ycomb_kernel<<<BB * CC * HH * 4, 256>>>(D_param);
    // 8) gated RMSNorm
    gatenorm_kernel<<<BB * LL, 256>>>(norm_w);
    // 9) out-projection GEMM (tf32)
    {
        dim3 grid(DM / 128, M / 128);
        tf32_gemm_kernel<<<grid, 256>>>(y_ptr, out_proj, out, M, DM, DI);
    }
    (void)in_sizes; (void)n_in; (void)out_size;
}